// round 2
// baseline (speedup 1.0000x reference)
#include <cuda_runtime.h>
#include <math.h>

// Problem constants (fixed shapes from reference setup_inputs)
#define MM   1024      // B*Q = 8*128
#define LN   8192      // number of labels
#define DD   300       // embedding dim
#define DP   304       // padded to multiple of BK=16
#define WW   16        // words per query
#define EPSV 1e-8f

// GEMM tiling
#define BM 64
#define BN 64
#define BK 16
#define TM 4
#define TN 4
#define GEMM_THREADS 256

// ---------------- scratch (device globals; no allocation allowed) ----------
__device__ __align__(16) float g_qe[MM * DP];   // query embeddings (mean), padded
__device__ __align__(16) float g_le[LN * DP];   // label embeddings, padded
__device__ float g_qn[MM];                      // ||q_e||
__device__ float g_ln[LN];                      // ||l_e||
__device__ float g_hasq[MM];                    // 1.0 if n_words != 0
__device__ float g_hasl[LN];                    // 1.0 if label != 0
__device__ int   g_idx64;                       // 1 if index buffers are int64

// ---------------------------------------------------------------------------
// Stage 0: detect whether the integer inputs are int64 or int32.
// For an int64 buffer holding values in [0, 50000), every odd 32-bit word
// (the high word) is zero. For an int32 buffer, odd positions are random
// label ids — all-zero has ~0 probability.
// Reads only LN int32 words: safe for both layouts.
// ---------------------------------------------------------------------------
__global__ void detect_dtype_kernel(const int* __restrict__ labels_raw)
{
    __shared__ int snz[8];
    const int t = threadIdx.x;           // 256 threads
    int nz = 0;
    for (int i = t * 2 + 1; i < LN; i += 512)   // odd positions
        nz |= (labels_raw[i] != 0);
    #pragma unroll
    for (int o = 16; o; o >>= 1) nz |= __shfl_xor_sync(0xffffffffu, nz, o);
    if ((t & 31) == 0) snz[t >> 5] = nz;
    __syncthreads();
    if (t == 0) {
        int a = 0;
        #pragma unroll
        for (int i = 0; i < 8; i++) a |= snz[i];
        g_idx64 = a ? 0 : 1;
    }
}

__device__ __forceinline__ long long load_index(const void* buf, int i)
{
    if (g_idx64) return ((const long long*)buf)[i];
    return (long long)((const int*)buf)[i];
}

// ---------------------------------------------------------------------------
// Stage 1: per-query mean of 16 gathered embedding rows + L2 norm
// grid = MM blocks, block = 320 threads (one thread per dim, 304 used)
// ---------------------------------------------------------------------------
__global__ __launch_bounds__(320) void query_embed_kernel(
    const float* __restrict__ emb, const void* __restrict__ queries, int nrows)
{
    const int row = blockIdx.x;
    const int d   = threadIdx.x;

    __shared__ int  sidx[WW];
    __shared__ float cnt_s;
    __shared__ float red[10];

    if (d < WW) {
        long long ix = load_index(queries, row * WW + d);
        if (ix < 0 || ix >= nrows) ix = 0;   // defensive clamp
        sidx[d] = (int)ix;
    }
    __syncthreads();

    if (d == 0) {
        int c = 0;
        #pragma unroll
        for (int w = 0; w < WW; w++) c += (sidx[w] != 0);
        cnt_s = (float)c;
    }

    float s = 0.f;
    if (d < DD) {
        #pragma unroll
        for (int w = 0; w < WW; w++) {
            size_t ix = (size_t)sidx[w];
            s += __ldg(&emb[ix * DD + d]);
        }
    }
    __syncthreads();

    const float cnt = cnt_s;
    float v = (d < DD) ? (s / cnt) : 0.f;
    if (d < DP) g_qe[(size_t)row * DP + d] = v;

    // block reduce sum of squares
    float sq = v * v;
    #pragma unroll
    for (int o = 16; o; o >>= 1) sq += __shfl_xor_sync(0xffffffffu, sq, o);
    if ((d & 31) == 0) red[d >> 5] = sq;
    __syncthreads();
    if (d == 0) {
        float t = 0.f;
        #pragma unroll
        for (int i = 0; i < 10; i++) t += red[i];
        g_qn[row]   = sqrtf(t);
        g_hasq[row] = (cnt != 0.f) ? 1.f : 0.f;
    }
}

// ---------------------------------------------------------------------------
// Stage 2: gather label embeddings + L2 norm
// grid = LN blocks, block = 320 threads
// ---------------------------------------------------------------------------
__global__ __launch_bounds__(320) void label_embed_kernel(
    const float* __restrict__ emb, const void* __restrict__ labels, int nrows)
{
    const int row = blockIdx.x;
    const int d   = threadIdx.x;
    __shared__ float red[10];
    __shared__ int six;
    __shared__ int snonzero;

    if (d == 0) {
        long long ixll = load_index(labels, row);
        snonzero = (ixll != 0);
        if (ixll < 0 || ixll >= nrows) ixll = 0;
        six = (int)ixll;
    }
    __syncthreads();

    const size_t ix = (size_t)six;
    float v = (d < DD) ? __ldg(&emb[ix * DD + d]) : 0.f;
    if (d < DP) g_le[(size_t)row * DP + d] = v;

    float sq = v * v;
    #pragma unroll
    for (int o = 16; o; o >>= 1) sq += __shfl_xor_sync(0xffffffffu, sq, o);
    if ((d & 31) == 0) red[d >> 5] = sq;
    __syncthreads();
    if (d == 0) {
        float t = 0.f;
        #pragma unroll
        for (int i = 0; i < 10; i++) t += red[i];
        g_ln[row]   = sqrtf(t);
        g_hasl[row] = snonzero ? 1.f : 0.f;
    }
}

// ---------------------------------------------------------------------------
// Stage 3: sim = (q_e . l_e) / max(|q_e||l_e|, eps)
// 64x64 block tile, 4x4 per-thread register tile, BK=16 smem-staged fp32 GEMM.
// ---------------------------------------------------------------------------
__global__ __launch_bounds__(GEMM_THREADS) void gemm_sim_kernel(
    float* __restrict__ out)
{
    __shared__ __align__(16) float As[BK][BM];
    __shared__ __align__(16) float Bs[BK][BN];

    const int tid = threadIdx.x;
    const int tx  = tid & 15;    // N direction
    const int ty  = tid >> 4;    // M direction
    const int m0  = blockIdx.y * BM;
    const int n0  = blockIdx.x * BN;

    // loader mapping: 256 threads load 64 rows x 16 k each (one float4/thread)
    const int lrow = tid >> 2;         // 0..63
    const int lk4  = (tid & 3) << 2;   // 0,4,8,12

    float acc[TM][TN];
    #pragma unroll
    for (int i = 0; i < TM; i++)
        #pragma unroll
        for (int j = 0; j < TN; j++) acc[i][j] = 0.f;

    const float* aGlob = &g_qe[(size_t)(m0 + lrow) * DP + lk4];
    const float* bGlob = &g_le[(size_t)(n0 + lrow) * DP + lk4];

    for (int k0 = 0; k0 < DP; k0 += BK) {
        float4 a = *(const float4*)(aGlob + k0);
        float4 b = *(const float4*)(bGlob + k0);
        As[lk4 + 0][lrow] = a.x; As[lk4 + 1][lrow] = a.y;
        As[lk4 + 2][lrow] = a.z; As[lk4 + 3][lrow] = a.w;
        Bs[lk4 + 0][lrow] = b.x; Bs[lk4 + 1][lrow] = b.y;
        Bs[lk4 + 2][lrow] = b.z; Bs[lk4 + 3][lrow] = b.w;
        __syncthreads();

        #pragma unroll
        for (int k = 0; k < BK; k++) {
            const float4 av = *(const float4*)&As[k][ty << 2];
            const float4 bv = *(const float4*)&Bs[k][tx << 2];
            const float aa[TM] = {av.x, av.y, av.z, av.w};
            const float bb[TN] = {bv.x, bv.y, bv.z, bv.w};
            #pragma unroll
            for (int i = 0; i < TM; i++)
                #pragma unroll
                for (int j = 0; j < TN; j++)
                    acc[i][j] = fmaf(aa[i], bb[j], acc[i][j]);
        }
        __syncthreads();
    }

    // epilogue: normalize and store
    float qn[TM], lnv[TN];
    #pragma unroll
    for (int i = 0; i < TM; i++) qn[i] = g_qn[m0 + (ty << 2) + i];
    #pragma unroll
    for (int j = 0; j < TN; j++) lnv[j] = g_ln[n0 + (tx << 2) + j];

    #pragma unroll
    for (int i = 0; i < TM; i++) {
        const int r = m0 + (ty << 2) + i;
        float4 o;
        float* po = (float*)&o;
        #pragma unroll
        for (int j = 0; j < TN; j++) {
            const float denom = fmaxf(qn[i] * lnv[j], EPSV);
            po[j] = acc[i][j] / denom;
        }
        *(float4*)&out[(size_t)r * LN + n0 + (tx << 2)] = o;
    }
}

// ---------------------------------------------------------------------------
// Mask writers. mask[b,q,0,l] = (n_words!=0) && (labels[l]!=0)
// ---------------------------------------------------------------------------
__global__ __launch_bounds__(256) void mask_float_kernel(float* __restrict__ outm)
{
    const int c = blockIdx.x * 256 + threadIdx.x;   // label index
    const int r = blockIdx.y;                       // query row
    const float v = g_hasq[r] * g_hasl[c];
    outm[(size_t)r * LN + c] = v;
}

__global__ __launch_bounds__(256) void mask_byte_kernel(unsigned char* __restrict__ outm)
{
    const int c = blockIdx.x * 256 + threadIdx.x;
    const int r = blockIdx.y;
    const unsigned char v = (g_hasq[r] != 0.f && g_hasl[c] != 0.f) ? 1 : 0;
    outm[(size_t)r * LN + c] = v;
}

// ---------------------------------------------------------------------------
extern "C" void kernel_launch(void* const* d_in, const int* in_sizes, int n_in,
                              void* d_out, int out_size)
{
    const float* emb     = (const float*)d_in[0];
    const void*  queries = d_in[1];
    const void*  labels  = d_in[2];
    float* out = (float*)d_out;

    const int emb_rows = in_sizes[0] / DD;   // 50000

    detect_dtype_kernel<<<1, 256>>>((const int*)labels);
    query_embed_kernel<<<MM, 320>>>(emb, queries, emb_rows);
    label_embed_kernel<<<LN, 320>>>(emb, labels, emb_rows);

    dim3 ggrid(LN / BN, MM / BM);
    gemm_sim_kernel<<<ggrid, GEMM_THREADS>>>(out);

    const long long NOUT = (long long)MM * (long long)LN;   // 8,388,608
    dim3 mgrid(LN / 256, MM);
    if ((long long)out_size >= 2 * NOUT) {
        // mask stored as float 0/1 after sim
        mask_float_kernel<<<mgrid, 256>>>(out + NOUT);
    } else if ((long long)out_size > NOUT) {
        // mask stored as packed bool bytes after sim
        mask_byte_kernel<<<mgrid, 256>>>((unsigned char*)(out + NOUT));
    }
    // if out_size == NOUT: only sim is expected; nothing else to write
}

// round 3
// speedup vs baseline: 1.2405x; 1.2405x over previous
#include <cuda_runtime.h>
#include <math.h>

// Problem constants (fixed shapes from reference setup_inputs)
#define MM   1024      // B*Q = 8*128
#define LN   8192      // number of labels
#define DD   300       // embedding dim
#define DP   304       // padded to multiple of BK=16
#define WW   16        // words per query
#define EPSV 1e-8f

// GEMM tiling
#define BM 128
#define BN 128
#define BK 16
#define NKT (DP / BK)   // 19 k-tiles
#define GEMM_THREADS 256

typedef unsigned long long u64;

// ---------------- scratch (device globals; no allocation allowed) ----------
__device__ __align__(16) float g_qe[MM * DP];   // query embeddings (mean), padded
__device__ __align__(16) float g_le[LN * DP];   // label embeddings, padded
__device__ float g_qn[MM];                      // ||q_e||
__device__ float g_ln[LN];                      // ||l_e||
__device__ float g_hasq[MM];                    // 1.0 if n_words != 0
__device__ float g_hasl[LN];                    // 1.0 if label != 0
__device__ int   g_idx64;                       // 1 if index buffers are int64

// ---------------- packed f32x2 helpers -------------------------------------
__device__ __forceinline__ u64 pack2(float x, float y) {
    u64 r;
    asm("mov.b64 %0, {%1, %2};" : "=l"(r) : "f"(x), "f"(y));
    return r;
}
__device__ __forceinline__ void unpack2(u64 v, float& x, float& y) {
    asm("mov.b64 {%0, %1}, %2;" : "=f"(x), "=f"(y) : "l"(v));
}
__device__ __forceinline__ void ffma2(u64& d, u64 a, u64 b) {
    asm("fma.rn.f32x2 %0, %1, %2, %0;" : "+l"(d) : "l"(a), "l"(b));
}

// ---------------------------------------------------------------------------
// Stage 0: detect whether the integer inputs are int64 or int32.
// ---------------------------------------------------------------------------
__global__ void detect_dtype_kernel(const int* __restrict__ labels_raw)
{
    __shared__ int snz[8];
    const int t = threadIdx.x;           // 256 threads
    int nz = 0;
    for (int i = t * 2 + 1; i < LN; i += 512)   // odd positions (int64 high words)
        nz |= (labels_raw[i] != 0);
    #pragma unroll
    for (int o = 16; o; o >>= 1) nz |= __shfl_xor_sync(0xffffffffu, nz, o);
    if ((t & 31) == 0) snz[t >> 5] = nz;
    __syncthreads();
    if (t == 0) {
        int a = 0;
        #pragma unroll
        for (int i = 0; i < 8; i++) a |= snz[i];
        g_idx64 = a ? 0 : 1;
    }
}

__device__ __forceinline__ long long load_index(const void* buf, int i)
{
    if (g_idx64) return ((const long long*)buf)[i];
    return (long long)((const int*)buf)[i];
}

// ---------------------------------------------------------------------------
// Stage 1: per-query mean of 16 gathered embedding rows + L2 norm
// ---------------------------------------------------------------------------
__global__ __launch_bounds__(320) void query_embed_kernel(
    const float* __restrict__ emb, const void* __restrict__ queries, int nrows)
{
    const int row = blockIdx.x;
    const int d   = threadIdx.x;

    __shared__ int   sidx[WW];
    __shared__ float cnt_s;
    __shared__ float red[10];

    if (d < WW) {
        long long ix = load_index(queries, row * WW + d);
        if (ix < 0 || ix >= nrows) ix = 0;   // defensive clamp
        sidx[d] = (int)ix;
    }
    __syncthreads();

    if (d == 0) {
        int c = 0;
        #pragma unroll
        for (int w = 0; w < WW; w++) c += (sidx[w] != 0);
        cnt_s = (float)c;
    }

    float s = 0.f;
    if (d < DD) {
        #pragma unroll
        for (int w = 0; w < WW; w++) {
            size_t ix = (size_t)sidx[w];
            s += __ldg(&emb[ix * DD + d]);
        }
    }
    __syncthreads();

    const float cnt = cnt_s;
    float v = (d < DD) ? (s / cnt) : 0.f;
    if (d < DP) g_qe[(size_t)row * DP + d] = v;

    float sq = v * v;
    #pragma unroll
    for (int o = 16; o; o >>= 1) sq += __shfl_xor_sync(0xffffffffu, sq, o);
    if ((d & 31) == 0) red[d >> 5] = sq;
    __syncthreads();
    if (d == 0) {
        float t = 0.f;
        #pragma unroll
        for (int i = 0; i < 10; i++) t += red[i];
        g_qn[row]   = sqrtf(t);
        g_hasq[row] = (cnt != 0.f) ? 1.f : 0.f;
    }
}

// ---------------------------------------------------------------------------
// Stage 2: gather label embeddings + L2 norm
// ---------------------------------------------------------------------------
__global__ __launch_bounds__(320) void label_embed_kernel(
    const float* __restrict__ emb, const void* __restrict__ labels, int nrows)
{
    const int row = blockIdx.x;
    const int d   = threadIdx.x;
    __shared__ float red[10];
    __shared__ int six;
    __shared__ int snonzero;

    if (d == 0) {
        long long ixll = load_index(labels, row);
        snonzero = (ixll != 0);
        if (ixll < 0 || ixll >= nrows) ixll = 0;
        six = (int)ixll;
    }
    __syncthreads();

    const size_t ix = (size_t)six;
    float v = (d < DD) ? __ldg(&emb[ix * DD + d]) : 0.f;
    if (d < DP) g_le[(size_t)row * DP + d] = v;

    float sq = v * v;
    #pragma unroll
    for (int o = 16; o; o >>= 1) sq += __shfl_xor_sync(0xffffffffu, sq, o);
    if ((d & 31) == 0) red[d >> 5] = sq;
    __syncthreads();
    if (d == 0) {
        float t = 0.f;
        #pragma unroll
        for (int i = 0; i < 10; i++) t += red[i];
        g_ln[row]   = sqrtf(t);
        g_hasl[row] = snonzero ? 1.f : 0.f;
    }
}

// ---------------------------------------------------------------------------
// Stage 3: sim GEMM. 128x128 tile, 8x8 register tile held as packed f32x2,
// BK=16, double-buffered smem with register prefetch. fma.rn.f32x2 inner loop.
// ---------------------------------------------------------------------------
__global__ __launch_bounds__(GEMM_THREADS, 2) void gemm_sim_kernel(
    float* __restrict__ out)
{
    __shared__ __align__(16) float As[2][BK][BM];
    __shared__ __align__(16) float Bs[2][BK][BN];

    const int tid = threadIdx.x;
    const int tx  = tid & 15;      // N direction: cols tx*8 .. tx*8+7
    const int ty  = tid >> 4;      // M direction: rows ty*8 .. ty*8+7
    const int m0  = blockIdx.y * BM;
    const int n0  = blockIdx.x * BN;

    // loader mapping: 256 threads, each loads 8 consecutive k of one row
    const int lrow = tid >> 1;           // 0..127
    const int lks  = (tid & 1) << 3;     // 0 or 8

    const float* aG = &g_qe[(size_t)(m0 + lrow) * DP + lks];
    const float* bG = &g_le[(size_t)(n0 + lrow) * DP + lks];

    u64 acc[8][4];
    #pragma unroll
    for (int i = 0; i < 8; i++)
        #pragma unroll
        for (int j = 0; j < 4; j++) acc[i][j] = 0ull;

    // load tile 0
    {
        float4 a0 = *(const float4*)(aG);
        float4 a1 = *(const float4*)(aG + 4);
        float4 b0 = *(const float4*)(bG);
        float4 b1 = *(const float4*)(bG + 4);
        As[0][lks + 0][lrow] = a0.x; As[0][lks + 1][lrow] = a0.y;
        As[0][lks + 2][lrow] = a0.z; As[0][lks + 3][lrow] = a0.w;
        As[0][lks + 4][lrow] = a1.x; As[0][lks + 5][lrow] = a1.y;
        As[0][lks + 6][lrow] = a1.z; As[0][lks + 7][lrow] = a1.w;
        Bs[0][lks + 0][lrow] = b0.x; Bs[0][lks + 1][lrow] = b0.y;
        Bs[0][lks + 2][lrow] = b0.z; Bs[0][lks + 3][lrow] = b0.w;
        Bs[0][lks + 4][lrow] = b1.x; Bs[0][lks + 5][lrow] = b1.y;
        Bs[0][lks + 6][lrow] = b1.z; Bs[0][lks + 7][lrow] = b1.w;
    }
    __syncthreads();

    #pragma unroll 1
    for (int t = 0; t < NKT; t++) {
        const int buf = t & 1;

        // prefetch next tile into registers
        float4 na0, na1, nb0, nb1;
        if (t < NKT - 1) {
            const float* ap = aG + (t + 1) * BK;
            const float* bp = bG + (t + 1) * BK;
            na0 = *(const float4*)(ap);
            na1 = *(const float4*)(ap + 4);
            nb0 = *(const float4*)(bp);
            nb1 = *(const float4*)(bp + 4);
        }

        #pragma unroll
        for (int k = 0; k < BK; k++) {
            const float4 av0 = *(const float4*)&As[buf][k][ty << 3];
            const float4 av1 = *(const float4*)&As[buf][k][(ty << 3) + 4];
            const float4 bv0 = *(const float4*)&Bs[buf][k][tx << 3];
            const float4 bv1 = *(const float4*)&Bs[buf][k][(tx << 3) + 4];

            u64 b2[4];
            b2[0] = pack2(bv0.x, bv0.y);
            b2[1] = pack2(bv0.z, bv0.w);
            b2[2] = pack2(bv1.x, bv1.y);
            b2[3] = pack2(bv1.z, bv1.w);

            const float aa[8] = {av0.x, av0.y, av0.z, av0.w,
                                 av1.x, av1.y, av1.z, av1.w};
            #pragma unroll
            for (int i = 0; i < 8; i++) {
                const u64 ad = pack2(aa[i], aa[i]);
                ffma2(acc[i][0], ad, b2[0]);
                ffma2(acc[i][1], ad, b2[1]);
                ffma2(acc[i][2], ad, b2[2]);
                ffma2(acc[i][3], ad, b2[3]);
            }
        }

        if (t < NKT - 1) {
            const int nb = buf ^ 1;
            As[nb][lks + 0][lrow] = na0.x; As[nb][lks + 1][lrow] = na0.y;
            As[nb][lks + 2][lrow] = na0.z; As[nb][lks + 3][lrow] = na0.w;
            As[nb][lks + 4][lrow] = na1.x; As[nb][lks + 5][lrow] = na1.y;
            As[nb][lks + 6][lrow] = na1.z; As[nb][lks + 7][lrow] = na1.w;
            Bs[nb][lks + 0][lrow] = nb0.x; Bs[nb][lks + 1][lrow] = nb0.y;
            Bs[nb][lks + 2][lrow] = nb0.z; Bs[nb][lks + 3][lrow] = nb0.w;
            Bs[nb][lks + 4][lrow] = nb1.x; Bs[nb][lks + 5][lrow] = nb1.y;
            Bs[nb][lks + 6][lrow] = nb1.z; Bs[nb][lks + 7][lrow] = nb1.w;
            __syncthreads();
        }
    }

    // epilogue: sim = dot * (1/qn) * (1/ln)   (norms >> eps for this data)
    float invq[8], invl[8];
    #pragma unroll
    for (int i = 0; i < 8; i++) {
        const float q = g_qn[m0 + (ty << 3) + i];
        invq[i] = __frcp_rn(fmaxf(q, 1e-12f));
    }
    #pragma unroll
    for (int j = 0; j < 8; j++) {
        const float l = g_ln[n0 + (tx << 3) + j];
        invl[j] = __frcp_rn(fmaxf(l, 1e-12f));
    }

    #pragma unroll
    for (int i = 0; i < 8; i++) {
        const int r = m0 + (ty << 3) + i;
        float v[8];
        unpack2(acc[i][0], v[0], v[1]);
        unpack2(acc[i][1], v[2], v[3]);
        unpack2(acc[i][2], v[4], v[5]);
        unpack2(acc[i][3], v[6], v[7]);
        float4 o0, o1;
        o0.x = v[0] * invq[i] * invl[0];
        o0.y = v[1] * invq[i] * invl[1];
        o0.z = v[2] * invq[i] * invl[2];
        o0.w = v[3] * invq[i] * invl[3];
        o1.x = v[4] * invq[i] * invl[4];
        o1.y = v[5] * invq[i] * invl[5];
        o1.z = v[6] * invq[i] * invl[6];
        o1.w = v[7] * invq[i] * invl[7];
        float* po = &out[(size_t)r * LN + n0 + (tx << 3)];
        *(float4*)(po)     = o0;
        *(float4*)(po + 4) = o1;
    }
}

// ---------------------------------------------------------------------------
// Mask writers. mask[b,q,0,l] = (n_words!=0) && (labels[l]!=0)
// ---------------------------------------------------------------------------
__global__ __launch_bounds__(256) void mask_float_kernel(float* __restrict__ outm)
{
    const int c4 = blockIdx.x * 256 + threadIdx.x;  // float4 index along labels
    const int r  = blockIdx.y;                      // query row
    const float hq = g_hasq[r];
    const int c = c4 << 2;
    float4 v;
    v.x = hq * g_hasl[c + 0];
    v.y = hq * g_hasl[c + 1];
    v.z = hq * g_hasl[c + 2];
    v.w = hq * g_hasl[c + 3];
    *(float4*)&outm[(size_t)r * LN + c] = v;
}

__global__ __launch_bounds__(256) void mask_byte_kernel(unsigned char* __restrict__ outm)
{
    const int c = blockIdx.x * 256 + threadIdx.x;
    const int r = blockIdx.y;
    const unsigned char v = (g_hasq[r] != 0.f && g_hasl[c] != 0.f) ? 1 : 0;
    outm[(size_t)r * LN + c] = v;
}

// ---------------------------------------------------------------------------
extern "C" void kernel_launch(void* const* d_in, const int* in_sizes, int n_in,
                              void* d_out, int out_size)
{
    const float* emb     = (const float*)d_in[0];
    const void*  queries = d_in[1];
    const void*  labels  = d_in[2];
    float* out = (float*)d_out;

    const int emb_rows = in_sizes[0] / DD;   // 50000

    detect_dtype_kernel<<<1, 256>>>((const int*)labels);
    query_embed_kernel<<<MM, 320>>>(emb, queries, emb_rows);
    label_embed_kernel<<<LN, 320>>>(emb, labels, emb_rows);

    dim3 ggrid(LN / BN, MM / BM);
    gemm_sim_kernel<<<ggrid, GEMM_THREADS>>>(out);

    const long long NOUT = (long long)MM * (long long)LN;   // 8,388,608
    if ((long long)out_size >= 2 * NOUT) {
        dim3 mgrid(LN / (256 * 4), MM);
        mask_float_kernel<<<mgrid, 256>>>(out + NOUT);
    } else if ((long long)out_size > NOUT) {
        dim3 mgrid(LN / 256, MM);
        mask_byte_kernel<<<mgrid, 256>>>((unsigned char*)(out + NOUT));
    }
}